// round 1
// baseline (speedup 1.0000x reference)
#include <cuda_runtime.h>

// FM second-order term:
//   out[b] = sum_e (features[b,:] @ W[:,e])^2  -  sum_f features[b,f]^2 * w2sum[f]
// with w2sum[f] = sum_e W[f,e]^2.
//
// B=16384, F=200, E=64. fp32 throughout (precision: W ~ 1e-4, FM cancellation).
// Strategy: FFMA2 (fma.rn.f32x2) packed fp32, W staged in smem in two F-halves,
// 4 threads per row (16 e-cols each), 32B-sector feature chunks with prefetch.

typedef unsigned long long ull;

__device__ __forceinline__ ull pack2(float a, float b) {
    ull r; asm("mov.b64 %0, {%1, %2};" : "=l"(r) : "f"(a), "f"(b)); return r;
}
__device__ __forceinline__ void ffma2(ull &d, ull a, ull b) {
    asm("fma.rn.f32x2 %0, %1, %2, %0;" : "+l"(d) : "l"(a), "l"(b));
}
__device__ __forceinline__ ull fmul2(ull a, ull b) {
    ull r; asm("mul.rn.f32x2 %0, %1, %2;" : "=l"(r) : "l"(a), "l"(b)); return r;
}
__device__ __forceinline__ ull fadd2(ull a, ull b) {
    ull r; asm("add.rn.f32x2 %0, %1, %2;" : "=l"(r) : "l"(a), "l"(b)); return r;
}
__device__ __forceinline__ float lohisum(ull v) {
    float lo, hi; asm("mov.b64 {%0, %1}, %2;" : "=f"(lo), "=f"(hi) : "l"(v)); return lo + hi;
}

constexpr int F_DIM = 200;
constexpr int E_DIM = 64;
constexpr int THREADS = 128;
constexpr int ROWS_PER_BLOCK = 32;   // 4 threads per row
constexpr int F0 = 104;              // half 0: f in [0,104)   -> 13 chunks of 8
constexpr int NC0 = 13;
constexpr int F1 = 96;               // half 1: f in [104,200) -> 12 chunks of 8
constexpr int NC1 = 12;

template <int NC>
__device__ __forceinline__ void process_half(
    const float* __restrict__ frow,   // features + row*F + fbase (32B aligned)
    const float* __restrict__ Ws,     // smem W half, [fcount][64]
    const ull*   __restrict__ w2u,    // smem w2sum as f32x2 pairs, offset fbase/2
    int q, ull acc[8], ull &sqa)
{
    const float4* fp4 = (const float4*)frow;
    float4 fa = fp4[0], fb = fp4[1];
    #pragma unroll 1
    for (int c = 0; c < NC; ++c) {
        // prefetch next chunk (clamped to chunk 0 on the last iter; discarded)
        int nxt = (c + 1 < NC) ? (c + 1) * 2 : 0;
        float4 na = fp4[nxt], nb = fp4[nxt + 1];

        float fv[8] = {fa.x, fa.y, fa.z, fa.w, fb.x, fb.y, fb.z, fb.w};
        #pragma unroll
        for (int j = 0; j < 8; ++j) {
            ull fpk = pack2(fv[j], fv[j]);
            const ulonglong2* wr =
                (const ulonglong2*)(Ws + (c * 8 + j) * E_DIM + q * 16);
            ulonglong2 w0 = wr[0], w1 = wr[1], w2 = wr[2], w3 = wr[3];
            ffma2(acc[0], fpk, w0.x); ffma2(acc[1], fpk, w0.y);
            ffma2(acc[2], fpk, w1.x); ffma2(acc[3], fpk, w1.y);
            ffma2(acc[4], fpk, w2.x); ffma2(acc[5], fpk, w2.y);
            ffma2(acc[6], fpk, w3.x); ffma2(acc[7], fpk, w3.y);
        }

        // squared-term: this lane owns f = c*8 + 2q, 2q+1 of this chunk
        float px = (q == 0) ? fa.x : (q == 1) ? fa.z : (q == 2) ? fb.x : fb.z;
        float py = (q == 0) ? fa.y : (q == 1) ? fa.w : (q == 2) ? fb.y : fb.w;
        ull fpair = pack2(px, py);
        ull fsq   = fmul2(fpair, fpair);
        ffma2(sqa, fsq, w2u[c * 4 + q]);

        fa = na; fb = nb;
    }
}

__global__ void __launch_bounds__(THREADS)
fm_kernel(const float* __restrict__ features,
          const float* __restrict__ W,
          float* __restrict__ out)
{
    __shared__ __align__(16) float Ws[F0 * E_DIM];   // 26.6 KB (max of halves)
    __shared__ __align__(16) float w2s[F_DIM];

    const int tid = threadIdx.x;

    // w2sum[f] = sum_e W[f,e]^2  (read from global; W is L2-resident)
    for (int f = tid; f < F_DIM; f += THREADS) {
        const float4* wr = (const float4*)(W + f * E_DIM);
        float s = 0.f;
        #pragma unroll
        for (int i = 0; i < E_DIM / 4; ++i) {
            float4 v = wr[i];
            s += v.x * v.x + v.y * v.y + v.z * v.z + v.w * v.w;
        }
        w2s[f] = s;
    }
    // stage W half 0 into smem
    {
        const float4* src = (const float4*)W;
        float4* dst = (float4*)Ws;
        for (int i = tid; i < F0 * E_DIM / 4; i += THREADS) dst[i] = src[i];
    }
    __syncthreads();

    const int q   = tid & 3;
    const int row = blockIdx.x * ROWS_PER_BLOCK + (tid >> 2);
    const float* frow = features + (size_t)row * F_DIM;

    ull acc[8];
    #pragma unroll
    for (int i = 0; i < 8; ++i) acc[i] = 0ull;
    ull sqa = 0ull;

    process_half<NC0>(frow, Ws, (const ull*)w2s, q, acc, sqa);

    __syncthreads();
    // stage W half 1
    {
        const float4* src = (const float4*)(W + F0 * E_DIM);
        float4* dst = (float4*)Ws;
        for (int i = tid; i < F1 * E_DIM / 4; i += THREADS) dst[i] = src[i];
    }
    __syncthreads();

    process_half<NC1>(frow + F0, Ws, (const ull*)w2s + F0 / 2, q, acc, sqa);

    // finalize: sum of squares of this lane's 16 e-accumulators, minus sq term
    ull s0 = fadd2(fmul2(acc[0], acc[0]), fmul2(acc[1], acc[1]));
    ull s1 = fadd2(fmul2(acc[2], acc[2]), fmul2(acc[3], acc[3]));
    ull s2 = fadd2(fmul2(acc[4], acc[4]), fmul2(acc[5], acc[5]));
    ull s3 = fadd2(fmul2(acc[6], acc[6]), fmul2(acc[7], acc[7]));
    ull s  = fadd2(fadd2(s0, s1), fadd2(s2, s3));

    float d = lohisum(s) - lohisum(sqa);
    d += __shfl_xor_sync(0xffffffffu, d, 1);
    d += __shfl_xor_sync(0xffffffffu, d, 2);
    if (q == 0) out[row] = d;
}

extern "C" void kernel_launch(void* const* d_in, const int* in_sizes, int n_in,
                              void* d_out, int out_size)
{
    const float* features = (const float*)d_in[0];
    const float* W        = (const float*)d_in[1];
    // safety: identify by size (features is the big one)
    if (n_in >= 2 && in_sizes[0] < in_sizes[1]) {
        features = (const float*)d_in[1];
        W        = (const float*)d_in[0];
    }
    float* out = (float*)d_out;

    const int B = out_size;                 // 16384 rows, [B,1] output
    const int blocks = B / ROWS_PER_BLOCK;  // 512
    fm_kernel<<<blocks, THREADS>>>(features, W, out);
}

// round 2
// speedup vs baseline: 3.0375x; 3.0375x over previous
#include <cuda_runtime.h>

// FM second-order term:
//   out[b] = sum_e (features[b,:] @ W[:,e])^2  -  sum_f features[b,f]^2 * w2sum[f]
// w2sum[f] = sum_e W[f,e]^2.   B=16384, F=200, E=64, fp32.
//
// R2: register row-tiling. 128-thr block = 8 row-groups x 16 e-groups.
// Thread: 8 rows x 4 e-cols (16 f32x2 accums). W via LDG (L1-resident, 51KB).
// Features LDG with 16-way warp dedup + ping-pong prefetch (L2-resident).
// sq term computed in a tail pass over per-eg feature slices.

typedef unsigned long long ull;

__device__ __forceinline__ ull pack2(float a, float b) {
    ull r; asm("mov.b64 %0, {%1, %2};" : "=l"(r) : "f"(a), "f"(b)); return r;
}
__device__ __forceinline__ void ffma2(ull &d, ull a, ull b) {
    asm("fma.rn.f32x2 %0, %1, %2, %0;" : "+l"(d) : "l"(a), "l"(b));
}
__device__ __forceinline__ ull fmul2(ull a, ull b) {
    ull r; asm("mul.rn.f32x2 %0, %1, %2;" : "=l"(r) : "l"(a), "l"(b)); return r;
}
__device__ __forceinline__ ull fadd2(ull a, ull b) {
    ull r; asm("add.rn.f32x2 %0, %1, %2;" : "=l"(r) : "l"(a), "l"(b)); return r;
}
__device__ __forceinline__ float lohisum(ull v) {
    float lo, hi; asm("mov.b64 {%0, %1}, %2;" : "=f"(lo), "=f"(hi) : "l"(v)); return lo + hi;
}

constexpr int F_DIM = 200;
constexpr int E_DIM = 64;
constexpr int THREADS = 128;
constexpr int RPT = 8;                 // rows per thread
constexpr int ROWS_PER_BLOCK = 64;     // 8 row-groups * 8 rows
constexpr int NCHUNK = F_DIM / 4;      // 50 chunks of 4 features

// one 4-feature chunk: prefetch fnxt (chunk nextc), consume fcur (chunk curc)
__device__ __forceinline__ void chunk_step(
    const float* __restrict__ frow, const float* __restrict__ Wq,
    int curc, int nextc, float4 fcur[RPT], float4 fnxt[RPT], ull acc[RPT][2])
{
    #pragma unroll
    for (int r = 0; r < RPT; ++r)
        fnxt[r] = *(const float4*)(frow + r * F_DIM + nextc * 4);

    ulonglong2 w[4];
    #pragma unroll
    for (int j = 0; j < 4; ++j)
        w[j] = *(const ulonglong2*)(Wq + (curc * 4 + j) * E_DIM);

    #pragma unroll
    for (int r = 0; r < RPT; ++r) {
        ull fp;
        fp = pack2(fcur[r].x, fcur[r].x);
        ffma2(acc[r][0], fp, w[0].x); ffma2(acc[r][1], fp, w[0].y);
        fp = pack2(fcur[r].y, fcur[r].y);
        ffma2(acc[r][0], fp, w[1].x); ffma2(acc[r][1], fp, w[1].y);
        fp = pack2(fcur[r].z, fcur[r].z);
        ffma2(acc[r][0], fp, w[2].x); ffma2(acc[r][1], fp, w[2].y);
        fp = pack2(fcur[r].w, fcur[r].w);
        ffma2(acc[r][0], fp, w[3].x); ffma2(acc[r][1], fp, w[3].y);
    }
}

__global__ void __launch_bounds__(THREADS)
fm_kernel(const float* __restrict__ features,
          const float* __restrict__ W,
          float* __restrict__ out)
{
    __shared__ __align__(16) float w2s[F_DIM];

    const int tid = threadIdx.x;
    const int eg  = tid & 15;          // e-group: columns eg*4 .. eg*4+3
    const int rg  = tid >> 4;          // row-group: rows rg*8 .. rg*8+7

    // w2sum[f] = sum_e W[f,e]^2
    for (int f = tid; f < F_DIM; f += THREADS) {
        const float4* wr = (const float4*)(W + f * E_DIM);
        float s = 0.f;
        #pragma unroll
        for (int i = 0; i < E_DIM / 4; ++i) {
            float4 v = wr[i];
            s += v.x * v.x + v.y * v.y + v.z * v.z + v.w * v.w;
        }
        w2s[f] = s;
    }
    __syncthreads();

    const int rowbase = blockIdx.x * ROWS_PER_BLOCK + rg * RPT;
    const float* frow = features + (size_t)rowbase * F_DIM;
    const float* Wq   = W + eg * 4;

    ull acc[RPT][2];
    #pragma unroll
    for (int r = 0; r < RPT; ++r) { acc[r][0] = 0ull; acc[r][1] = 0ull; }

    float4 fa[RPT], fb[RPT];
    #pragma unroll
    for (int r = 0; r < RPT; ++r)
        fa[r] = *(const float4*)(frow + r * F_DIM);

    #pragma unroll 1
    for (int c = 0; c < NCHUNK; c += 2) {
        chunk_step(frow, Wq, c,     c + 1,                          fa, fb, acc);
        chunk_step(frow, Wq, c + 1, (c + 2 < NCHUNK) ? c + 2 : 0,   fb, fa, acc);
    }

    // ---- squared-term tail: eg owns a contiguous slice of 4-f chunks ----
    // chunk counts: egs 0,1 -> 4 chunks; egs 2..15 -> 3 chunks (2*4+14*3=50)
    const int c0   = (eg < 2) ? eg * 4 : 8 + (eg - 2) * 3;
    const int ccnt = (eg < 2) ? 4 : 3;

    ull sq2[RPT];
    #pragma unroll
    for (int r = 0; r < RPT; ++r) sq2[r] = 0ull;

    #pragma unroll
    for (int k = 0; k < 4; ++k) {
        if (k < ccnt) {
            const int c = c0 + k;
            const ull w01 = *(const ull*)(w2s + c * 4);
            const ull w23 = *(const ull*)(w2s + c * 4 + 2);
            #pragma unroll
            for (int r = 0; r < RPT; ++r) {
                float4 fv = *(const float4*)(frow + r * F_DIM + c * 4);
                ull p01 = pack2(fv.x, fv.y);
                ull p23 = pack2(fv.z, fv.w);
                ffma2(sq2[r], fmul2(p01, p01), w01);
                ffma2(sq2[r], fmul2(p23, p23), w23);
            }
        }
    }

    // ---- finalize: per-row sum of acc^2 minus sq, reduce over 16 e-groups ----
    #pragma unroll
    for (int r = 0; r < RPT; ++r) {
        ull t = fadd2(fmul2(acc[r][0], acc[r][0]), fmul2(acc[r][1], acc[r][1]));
        float d = lohisum(t) - lohisum(sq2[r]);
        d += __shfl_xor_sync(0xffffffffu, d, 1);
        d += __shfl_xor_sync(0xffffffffu, d, 2);
        d += __shfl_xor_sync(0xffffffffu, d, 4);
        d += __shfl_xor_sync(0xffffffffu, d, 8);
        if (eg == 0) out[rowbase + r] = d;
    }
}

extern "C" void kernel_launch(void* const* d_in, const int* in_sizes, int n_in,
                              void* d_out, int out_size)
{
    const float* features = (const float*)d_in[0];
    const float* W        = (const float*)d_in[1];
    if (n_in >= 2 && in_sizes[0] < in_sizes[1]) {
        features = (const float*)d_in[1];
        W        = (const float*)d_in[0];
    }
    float* out = (float*)d_out;

    const int B = out_size;                      // 16384
    const int blocks = B / ROWS_PER_BLOCK;       // 256
    fm_kernel<<<blocks, THREADS>>>(features, W, out);
}